// round 1
// baseline (speedup 1.0000x reference)
#include <cuda_runtime.h>
#include <math.h>

#define B_ 512
#define T_ 96
#define F_ 128
#define H_ 512
#define TB_ (T_*B_)        // 49152
#define BTF_ (B_*T_*F_)    // 6291456
#define KG_ 768            // gates GEMM K = 2F + H
#define NG_ 2048           // 4H

// ---------------- scratch (device globals: no allocation allowed) ----------------
__device__ float g_delta[TB_*F_];            // [t,b,f]
__device__ float g_gammah[TB_*H_];           // [t,b,h]  (~100MB)
__device__ float g_A2[TB_*2*F_];             // [t,b, gx|m]
__device__ float g_alpha[TB_*F_];            // [t,b,f]
__device__ float g_Abuf[B_*KG_];             // per-step GEMM A = [c_c | m | h*gamma]
__device__ float g_gates[B_*NG_];            // per-step gates
__device__ float g_c[B_*H_];                 // LSTM cell state carry
__device__ float g_Wg[NG_*KG_];              // [Wih | Whh] fused
__device__ float g_bg[NG_];                  // bih + bhh

__device__ __forceinline__ float sigmoidf_(float v){ return 1.f/(1.f+expf(-v)); }

// ---------------- setup: fuse LSTM weights ----------------
__global__ void k_setup(const float* __restrict__ Wih, const float* __restrict__ Whh,
                        const float* __restrict__ bih, const float* __restrict__ bhh){
    int tid0 = blockIdx.x*blockDim.x + threadIdx.x;
    for (int idx = tid0; idx < NG_*KG_; idx += gridDim.x*blockDim.x){
        int n = idx / KG_;
        int k = idx - n*KG_;
        g_Wg[idx] = (k < 256) ? Wih[n*256 + k] : Whh[n*H_ + (k-256)];
    }
    if (tid0 < NG_) g_bg[tid0] = bih[tid0] + bhh[tid0];
}

// ---------------- delta scan (parallel over B*F, sequential over T) ----------------
__global__ void k_delta(const int* __restrict__ mask){
    int idx = blockIdx.x*blockDim.x + threadIdx.x;   // B*F = 65536
    int b = idx >> 7, f = idx & 127;
    const int base = b*T_*F_ + f;
    float d = 0.f;
    #pragma unroll 4
    for (int t = 0; t < T_; t++){
        g_delta[t*B_*F_ + b*F_ + f] = d;
        float mp = (float)mask[base + t*F_];
        d = mp + (1.f - mp)*(d + 1.f);
    }
}

// ---------------- gamma_x + alpha-input assembly ----------------
__global__ void k_gx(const int* __restrict__ mask, const float* __restrict__ Wdx,
                     const float* __restrict__ bdx){
    int idx = blockIdx.x*blockDim.x + threadIdx.x;   // TB*F
    if (idx >= TB_*F_) return;
    int r = idx >> 7, f = idx & 127;
    int t = r / B_, b = r - t*B_;
    float d  = g_delta[idx];
    float gx = expf(-fmaxf(d * Wdx[f*F_ + f] + bdx[f], 0.f));
    g_A2[r*256 + f]       = gx;
    g_A2[r*256 + 128 + f] = (float)mask[b*T_*F_ + t*F_ + f];
}

// ---------------- generic fp32 GEMM: C[M,N] = A[M,K] @ W[N,K]^T + bias, + epilogue -----
// tile 128(M) x 64(N), 256 threads, 8x4 register tile. M%128==0, N%64==0, K%16==0.
// EPI: 0 = none, 1 = exp(-relu(v)), 2 = sigmoid(v)
template<int EPI>
__global__ void __launch_bounds__(256, 4)
gemm_nt(const float* __restrict__ A, int lda,
        const float* __restrict__ W, int ldw,
        const float* __restrict__ bias,
        float* __restrict__ C, int ldc, int K)
{
    __shared__ float As[16][132];   // [k][m], padded
    __shared__ float Bs[16][68];    // [k][n], padded
    const int tid = threadIdx.x;
    const int m0 = blockIdx.y * 128;
    const int n0 = blockIdx.x * 64;
    const int tx = tid & 15;        // n-sub: tx*4
    const int ty = tid >> 4;        // m-sub: ty*8
    const int lrow = tid >> 2;      // 0..63
    const int lc   = (tid & 3) << 2;

    float acc[8][4];
    #pragma unroll
    for (int i = 0; i < 8; i++)
        #pragma unroll
        for (int j = 0; j < 4; j++) acc[i][j] = 0.f;

    for (int k0 = 0; k0 < K; k0 += 16){
        float4 a0 = *(const float4*)&A[(size_t)(m0+lrow   )*lda + k0 + lc];
        float4 a1 = *(const float4*)&A[(size_t)(m0+lrow+64)*lda + k0 + lc];
        float4 bv = *(const float4*)&W[(size_t)(n0+lrow   )*ldw + k0 + lc];
        As[lc+0][lrow]    = a0.x; As[lc+1][lrow]    = a0.y;
        As[lc+2][lrow]    = a0.z; As[lc+3][lrow]    = a0.w;
        As[lc+0][lrow+64] = a1.x; As[lc+1][lrow+64] = a1.y;
        As[lc+2][lrow+64] = a1.z; As[lc+3][lrow+64] = a1.w;
        Bs[lc+0][lrow] = bv.x; Bs[lc+1][lrow] = bv.y;
        Bs[lc+2][lrow] = bv.z; Bs[lc+3][lrow] = bv.w;
        __syncthreads();
        #pragma unroll
        for (int kk = 0; kk < 16; kk++){
            float4 av0 = *(const float4*)&As[kk][ty*8];
            float4 av1 = *(const float4*)&As[kk][ty*8+4];
            float4 b4  = *(const float4*)&Bs[kk][tx*4];
            float am[8] = {av0.x,av0.y,av0.z,av0.w,av1.x,av1.y,av1.z,av1.w};
            float bn[4] = {b4.x,b4.y,b4.z,b4.w};
            #pragma unroll
            for (int i = 0; i < 8; i++)
                #pragma unroll
                for (int j = 0; j < 4; j++)
                    acc[i][j] += am[i]*bn[j];
        }
        __syncthreads();
    }

    float4 bia = *(const float4*)&bias[n0 + tx*4];
    float bj[4] = {bia.x, bia.y, bia.z, bia.w};
    #pragma unroll
    for (int i = 0; i < 8; i++){
        int m = m0 + ty*8 + i;
        #pragma unroll
        for (int j = 0; j < 4; j++){
            float v = acc[i][j] + bj[j];
            if (EPI == 1)      v = expf(-fmaxf(v, 0.f));
            else if (EPI == 2) v = 1.f/(1.f+expf(-v));
            C[(size_t)m*ldc + n0 + tx*4 + j] = v;
        }
    }
}

// ---------------- per-step fused kernel ----------------
// 64 CTAs x 256 threads; each CTA owns 8 batch rows.
// Phase 1: LSTM update from previous gates -> h (smem), c (gmem); write decayed-h into A.
// Phase 2: x_h = h @ Wh^T + bh (Wh staged transposed in smem chunks).
// Phase 3: z_h = x_c @ Wf^T (off-diag) + bf; c_h, c_c; write outputs + A[c_c|m].
__global__ void __launch_bounds__(256)
k_step(int t, const float* __restrict__ x, const int* __restrict__ mask,
       const float* __restrict__ Wh, const float* __restrict__ bh,
       const float* __restrict__ Wf, const float* __restrict__ bf,
       float* __restrict__ out)
{
    __shared__ float hs[8][512];
    __shared__ float Wt[32][129];
    __shared__ float xh_s[8][128];
    __shared__ float xc_s[8][128];
    __shared__ float wfdiag[128];
    const int tid = threadIdx.x;
    const int b0  = blockIdx.x << 3;

    if (tid < 128) wfdiag[tid] = Wf[tid*F_ + tid];

    // ---- Phase 1: carry update ----
    if (t == 0){
        for (int idx = tid; idx < 8*512; idx += 256){
            int b = idx >> 9, j = idx & 511;
            hs[b][j] = 0.f;
            g_c[(b0+b)*H_ + j] = 0.f;
            g_Abuf[(b0+b)*KG_ + 256 + j] = 0.f;    // h*gamma = 0
        }
    } else {
        for (int idx = tid; idx < 8*512; idx += 256){
            int b = idx >> 9, j = idx & 511;
            int gb = b0 + b;
            const float* grow = &g_gates[gb*NG_];
            float ig = sigmoidf_(grow[j]);
            float fg = sigmoidf_(grow[512 + j]);
            float gg = tanhf    (grow[1024 + j]);
            float og = sigmoidf_(grow[1536 + j]);
            float c  = fg * g_c[gb*H_ + j] + ig*gg;
            g_c[gb*H_ + j] = c;
            float h  = og * tanhf(c);
            hs[b][j] = h;
            g_Abuf[gb*KG_ + 256 + j] = h * g_gammah[(t*B_ + gb)*H_ + j];
        }
    }
    __syncthreads();

    const int n   = tid & 127;       // output feature
    const int bh2 = tid >> 7;        // 0/1 -> rows {bh2*4 .. bh2*4+3}

    // ---- Phase 2: x_h ----
    float acc[4] = {0.f,0.f,0.f,0.f};
    for (int k0 = 0; k0 < H_; k0 += 32){
        for (int idx = tid; idx < 128*32; idx += 256){
            int nn = idx >> 5, kk = idx & 31;
            Wt[kk][nn] = Wh[nn*H_ + k0 + kk];
        }
        __syncthreads();
        #pragma unroll
        for (int k4 = 0; k4 < 8; k4++){
            float4 hv0 = *(const float4*)&hs[bh2*4+0][k0 + k4*4];
            float4 hv1 = *(const float4*)&hs[bh2*4+1][k0 + k4*4];
            float4 hv2 = *(const float4*)&hs[bh2*4+2][k0 + k4*4];
            float4 hv3 = *(const float4*)&hs[bh2*4+3][k0 + k4*4];
            #pragma unroll
            for (int c2 = 0; c2 < 4; c2++){
                float w = Wt[k4*4 + c2][n];
                acc[0] += w * ((&hv0.x)[c2]);
                acc[1] += w * ((&hv1.x)[c2]);
                acc[2] += w * ((&hv2.x)[c2]);
                acc[3] += w * ((&hv3.x)[c2]);
            }
        }
        __syncthreads();
    }

    float m_r[4], x_r[4];
    {
        float bhv = bh[n];
        #pragma unroll
        for (int i = 0; i < 4; i++){
            int b = bh2*4 + i, gb = b0 + b;
            float xh = acc[i] + bhv;
            xh_s[b][n] = xh;
            int gi = gb*T_*F_ + t*F_ + n;
            float mv = (float)mask[gi];
            float xv = x[gi];
            m_r[i] = mv; x_r[i] = xv;
            xc_s[b][n] = mv*xv + (1.f - mv)*xh;
            out[3*BTF_ + gi] = xh;
        }
    }
    __syncthreads();

    // ---- Phase 3: z_h ----
    float acc2[4] = {0.f,0.f,0.f,0.f};
    for (int k0 = 0; k0 < F_; k0 += 32){
        for (int idx = tid; idx < 128*32; idx += 256){
            int nn = idx >> 5, kk = idx & 31;
            Wt[kk][nn] = Wf[nn*F_ + k0 + kk];
        }
        __syncthreads();
        #pragma unroll
        for (int k4 = 0; k4 < 8; k4++){
            float4 v0 = *(const float4*)&xc_s[bh2*4+0][k0 + k4*4];
            float4 v1 = *(const float4*)&xc_s[bh2*4+1][k0 + k4*4];
            float4 v2 = *(const float4*)&xc_s[bh2*4+2][k0 + k4*4];
            float4 v3 = *(const float4*)&xc_s[bh2*4+3][k0 + k4*4];
            #pragma unroll
            for (int c2 = 0; c2 < 4; c2++){
                float w = Wt[k4*4 + c2][n];
                acc2[0] += w * ((&v0.x)[c2]);
                acc2[1] += w * ((&v1.x)[c2]);
                acc2[2] += w * ((&v2.x)[c2]);
                acc2[3] += w * ((&v3.x)[c2]);
            }
        }
        __syncthreads();
    }

    {
        float bfv = bf[n];
        #pragma unroll
        for (int i = 0; i < 4; i++){
            int b = bh2*4 + i, gb = b0 + b;
            float z  = acc2[i] + bfv - xc_s[b][n]*wfdiag[n];   // off-diagonal mask
            float al = g_alpha[(t*B_ + gb)*F_ + n];
            float xh = xh_s[b][n];
            float ch = al*z + (1.f - al)*xh;
            float cc = m_r[i]*x_r[i] + (1.f - m_r[i])*ch;
            int gi = gb*T_*F_ + t*F_ + n;
            out[gi]          = cc;   // imputation
            out[BTF_  + gi]  = ch;
            out[2*BTF_+ gi]  = z;
            g_Abuf[gb*KG_ + n]       = cc;
            g_Abuf[gb*KG_ + 128 + n] = m_r[i];
        }
    }
}

// ---------------- launch ----------------
extern "C" void kernel_launch(void* const* d_in, const int* in_sizes, int n_in,
                              void* d_out, int out_size)
{
    const float* x    = (const float*)d_in[0];
    const int*   mask = (const int*  )d_in[1];
    const float* Wdh  = (const float*)d_in[2];
    const float* bdh  = (const float*)d_in[3];
    const float* Wdx  = (const float*)d_in[4];
    const float* bdx  = (const float*)d_in[5];
    const float* Wh   = (const float*)d_in[6];
    const float* bh   = (const float*)d_in[7];
    const float* Wf   = (const float*)d_in[8];
    const float* bf   = (const float*)d_in[9];
    const float* Wc   = (const float*)d_in[10];
    const float* bc   = (const float*)d_in[11];
    const float* Wih  = (const float*)d_in[12];
    const float* Whh  = (const float*)d_in[13];
    const float* bih  = (const float*)d_in[14];
    const float* bhh  = (const float*)d_in[15];
    float* out = (float*)d_out;

    float *pDelta, *pGammah, *pA2, *pAlpha, *pA, *pGates, *pWg, *pBg;
    cudaGetSymbolAddress((void**)&pDelta,  g_delta);
    cudaGetSymbolAddress((void**)&pGammah, g_gammah);
    cudaGetSymbolAddress((void**)&pA2,     g_A2);
    cudaGetSymbolAddress((void**)&pAlpha,  g_alpha);
    cudaGetSymbolAddress((void**)&pA,      g_Abuf);
    cudaGetSymbolAddress((void**)&pGates,  g_gates);
    cudaGetSymbolAddress((void**)&pWg,     g_Wg);
    cudaGetSymbolAddress((void**)&pBg,     g_bg);

    // setup + time-parallel precomputes
    k_setup<<<6144, 256>>>(Wih, Whh, bih, bhh);
    k_delta<<<256, 256>>>(mask);
    // gamma_h = exp(-relu(delta @ Wdh^T + bdh)) : [49152,128]@[128,512]
    gemm_nt<1><<<dim3(H_/64, TB_/128), 256>>>(pDelta, F_, Wdh, F_, bdh, pGammah, H_, F_);
    k_gx<<<(TB_*F_ + 255)/256, 256>>>(mask, Wdx, bdx);
    // alpha = sigmoid([gx,m] @ Wc^T + bc) : [49152,256]@[256,128]
    gemm_nt<2><<<dim3(F_/64, TB_/128), 256>>>(pA2, 2*F_, Wc, 2*F_, bc, pAlpha, F_, 2*F_);

    // sequential recurrence: 96 steps
    for (int t = 0; t < T_; t++){
        k_step<<<64, 256>>>(t, x, mask, Wh, bh, Wf, bf, out);
        if (t < T_ - 1){
            // gates = A @ Wg^T + bg : [512,768]@[768,2048]
            gemm_nt<0><<<dim3(NG_/64, B_/128), 256>>>(pA, KG_, pWg, KG_, pBg, pGates, NG_, KG_);
        }
    }
}

// round 4
// speedup vs baseline: 1.5765x; 1.5765x over previous
#include <cuda_runtime.h>
#include <cuda_bf16.h>
#include <cstdint>
#include <math.h>

#define B_ 512
#define T_ 96
#define F_ 128
#define H_ 512
#define TB_ (T_*B_)        // 49152
#define BTF_ (B_*T_*F_)    // 6291456
#define KG_ 768            // gates GEMM K = 2F + H
#define NG_ 2048           // 4H

typedef unsigned int u32;

// ---------------- scratch (device globals: no allocation allowed) ----------------
__device__ float g_delta[TB_*F_];                         // [t,b,f] fp32
__device__ __align__(16) __nv_bfloat16 g_dhi[TB_*F_];     // delta hi/lo
__device__ __align__(16) __nv_bfloat16 g_dlo[TB_*F_];
__device__ float g_gammah[TB_*H_];                        // [t*B+b, h]
__device__ __align__(16) __nv_bfloat16 g_A2hi[TB_*2*F_];  // [t*B+b, gx|m]
__device__ __align__(16) __nv_bfloat16 g_A2lo[TB_*2*F_];
__device__ float g_alpha[TB_*F_];
__device__ __align__(16) __nv_bfloat16 g_Ahi[B_*KG_];     // per-step A = [c_c | m | h*gamma]
__device__ __align__(16) __nv_bfloat16 g_Alo[B_*KG_];
__device__ float g_gates[B_*NG_];
__device__ float g_c[B_*H_];
__device__ __align__(16) __nv_bfloat16 g_Wghi[NG_*KG_];   // [Wih | Whh] fused, split
__device__ __align__(16) __nv_bfloat16 g_Wglo[NG_*KG_];
__device__ float g_bg[NG_];
__device__ __align__(16) __nv_bfloat16 g_Wdhhi[H_*F_];
__device__ __align__(16) __nv_bfloat16 g_Wdhlo[H_*F_];
__device__ __align__(16) __nv_bfloat16 g_Wchi[F_*2*F_];
__device__ __align__(16) __nv_bfloat16 g_Wclo[F_*2*F_];

__device__ __forceinline__ float sigmoidf_(float v){ return 1.f/(1.f+expf(-v)); }

__device__ __forceinline__ void bsplit(float v, __nv_bfloat16* hi, __nv_bfloat16* lo){
    __nv_bfloat16 h = __float2bfloat16(v);
    *hi = h;
    *lo = __float2bfloat16(v - __bfloat162float(h));
}

__device__ __forceinline__ u32 sptr(const void* p){
    return (u32)__cvta_generic_to_shared(p);
}

__device__ __forceinline__ void ldsm4(u32* r, u32 addr){
    asm volatile("ldmatrix.sync.aligned.m8n8.x4.shared.b16 {%0,%1,%2,%3}, [%4];"
        : "=r"(r[0]),"=r"(r[1]),"=r"(r[2]),"=r"(r[3]) : "r"(addr));
}

__device__ __forceinline__ void mma16816(float* c, const u32* a, u32 b0, u32 b1){
    asm volatile("mma.sync.aligned.m16n8k16.row.col.f32.bf16.bf16.f32 "
        "{%0,%1,%2,%3},{%4,%5,%6,%7},{%8,%9},{%0,%1,%2,%3};"
        : "+f"(c[0]),"+f"(c[1]),"+f"(c[2]),"+f"(c[3])
        : "r"(a[0]),"r"(a[1]),"r"(a[2]),"r"(a[3]), "r"(b0),"r"(b1));
}

// ---------------- setup: fuse + split all weights ----------------
__global__ void k_setup(const float* __restrict__ Wih, const float* __restrict__ Whh,
                        const float* __restrict__ bih, const float* __restrict__ bhh,
                        const float* __restrict__ Wdh, const float* __restrict__ Wc){
    int tid0 = blockIdx.x*blockDim.x + threadIdx.x;
    int stride = gridDim.x*blockDim.x;
    for (int idx = tid0; idx < NG_*KG_; idx += stride){
        int n = idx / KG_;
        int k = idx - n*KG_;
        float v = (k < 256) ? Wih[n*256 + k] : Whh[n*H_ + (k-256)];
        bsplit(v, &g_Wghi[idx], &g_Wglo[idx]);
    }
    for (int idx = tid0; idx < H_*F_; idx += stride)
        bsplit(Wdh[idx], &g_Wdhhi[idx], &g_Wdhlo[idx]);
    for (int idx = tid0; idx < F_*2*F_; idx += stride)
        bsplit(Wc[idx], &g_Wchi[idx], &g_Wclo[idx]);
    if (tid0 < NG_) g_bg[tid0] = bih[tid0] + bhh[tid0];
}

// ---------------- delta scan ----------------
__global__ void k_delta(const int* __restrict__ mask){
    int idx = blockIdx.x*blockDim.x + threadIdx.x;   // B*F = 65536
    int b = idx >> 7, f = idx & 127;
    const int base = b*T_*F_ + f;
    float d = 0.f;
    #pragma unroll 4
    for (int t = 0; t < T_; t++){
        int o = t*B_*F_ + b*F_ + f;
        g_delta[o] = d;
        bsplit(d, &g_dhi[o], &g_dlo[o]);
        float mp = (float)mask[base + t*F_];
        d = mp + (1.f - mp)*(d + 1.f);
    }
}

// ---------------- gamma_x + alpha-input assembly ----------------
__global__ void k_gx(const int* __restrict__ mask, const float* __restrict__ Wdx,
                     const float* __restrict__ bdx){
    int idx = blockIdx.x*blockDim.x + threadIdx.x;   // TB*F
    if (idx >= TB_*F_) return;
    int r = idx >> 7, f = idx & 127;
    int t = r / B_, b = r - t*B_;
    float d  = g_delta[idx];
    float gx = expf(-fmaxf(d * Wdx[f*F_ + f] + bdx[f], 0.f));
    bsplit(gx, &g_A2hi[r*256 + f], &g_A2lo[r*256 + f]);
    float mv = (float)mask[b*T_*F_ + t*F_ + f];
    g_A2hi[r*256 + 128 + f] = __float2bfloat16(mv);
    g_A2lo[r*256 + 128 + f] = __float2bfloat16(0.f);
}

// ---------------- split-bf16 tensor-core GEMM ----------------
// C[M,N] = (Ahi+Alo)[M,K] @ (Whi+Wlo)[N,K]^T + bias (3-pass Markidis split)
// CTA tile 64(M) x 128(N), BK=64, 256 threads = 8 warps (2M x 4N), warp tile 32x32.
// EPI: 0 none, 1 exp(-relu(v)), 2 sigmoid(v). Requires M%64==0, N%128==0, K%64==0.
#define SSTR 72   // smem row stride in bf16 (144B = 9*16B: aligned + LDSM conflict-free)
template<int EPI>
__global__ void __launch_bounds__(256, 1)
gemm_sp(const __nv_bfloat16* __restrict__ Ahi, const __nv_bfloat16* __restrict__ Alo,
        const __nv_bfloat16* __restrict__ Whi, const __nv_bfloat16* __restrict__ Wlo,
        const float* __restrict__ bias, float* __restrict__ C, int N, int K)
{
    __shared__ __align__(16) __nv_bfloat16 As[64*SSTR];
    __shared__ __align__(16) __nv_bfloat16 Ws[128*SSTR];
    const int tid = threadIdx.x, lane = tid & 31, wid = tid >> 5;
    const int m0 = blockIdx.y*64, n0 = blockIdx.x*128;
    const int wm = (wid & 1)*32, wn = (wid >> 1)*32;

    float acc[2][4][4];
    #pragma unroll
    for (int i=0;i<2;i++)
        #pragma unroll
        for (int j=0;j<4;j++)
            #pragma unroll
            for (int q=0;q<4;q++) acc[i][j][q] = 0.f;

    // lane-local ldmatrix coordinates
    const int aRow = lane & 15;
    const int aCol = ((lane >> 4) & 1) * 8;
    const int bRow = (lane & 7) + ((lane >> 4) & 1) * 8;
    const int bCol = ((lane >> 3) & 1) * 8;

    for (int pass = 0; pass < 3; pass++){
        const __nv_bfloat16* Ap = (pass == 1) ? Alo : Ahi;
        const __nv_bfloat16* Wp = (pass == 2) ? Wlo : Whi;
        for (int k0 = 0; k0 < K; k0 += 64){
            #pragma unroll
            for (int i = 0; i < 2; i++){
                int u = tid + i*256; int r = u >> 3, cu = (u & 7) * 8;
                *(uint4*)&As[r*SSTR + cu] = *(const uint4*)&Ap[(size_t)(m0+r)*K + k0 + cu];
            }
            #pragma unroll
            for (int i = 0; i < 4; i++){
                int u = tid + i*256; int r = u >> 3, cu = (u & 7) * 8;
                *(uint4*)&Ws[r*SSTR + cu] = *(const uint4*)&Wp[(size_t)(n0+r)*K + k0 + cu];
            }
            __syncthreads();
            #pragma unroll
            for (int kk = 0; kk < 64; kk += 16){
                u32 a[2][4], b[2][4];
                #pragma unroll
                for (int mt = 0; mt < 2; mt++)
                    ldsm4(a[mt], sptr(&As[(wm + mt*16 + aRow)*SSTR + kk + aCol]));
                #pragma unroll
                for (int nt = 0; nt < 2; nt++)
                    ldsm4(b[nt], sptr(&Ws[(wn + nt*16 + bRow)*SSTR + kk + bCol]));
                #pragma unroll
                for (int mt = 0; mt < 2; mt++)
                    #pragma unroll
                    for (int nj = 0; nj < 4; nj++){
                        const u32* bb = &b[nj >> 1][(nj & 1) * 2];
                        mma16816(acc[mt][nj], a[mt], bb[0], bb[1]);
                    }
            }
            __syncthreads();
        }
    }

    #pragma unroll
    for (int mt = 0; mt < 2; mt++){
        int row = m0 + wm + mt*16 + (lane >> 2);
        #pragma unroll
        for (int nj = 0; nj < 4; nj++){
            int col = n0 + wn + nj*8 + (lane & 3)*2;
            float b0v = bias[col], b1v = bias[col+1];
            float v[4] = { acc[mt][nj][0] + b0v, acc[mt][nj][1] + b1v,
                           acc[mt][nj][2] + b0v, acc[mt][nj][3] + b1v };
            #pragma unroll
            for (int q = 0; q < 4; q++){
                if (EPI == 1)      v[q] = expf(-fmaxf(v[q], 0.f));
                else if (EPI == 2) v[q] = 1.f/(1.f+expf(-v[q]));
            }
            C[(size_t)row*N + col]     = v[0];
            C[(size_t)row*N + col + 1] = v[1];
            C[(size_t)(row+8)*N + col]     = v[2];
            C[(size_t)(row+8)*N + col + 1] = v[3];
        }
    }
}

// ---------------- per-step fused kernel ----------------
// 128 CTAs x 256 threads; each CTA owns 4 batch rows.
__global__ void __launch_bounds__(256)
k_step(int t, const float* __restrict__ x, const int* __restrict__ mask,
       const float* __restrict__ Wh, const float* __restrict__ bh,
       const float* __restrict__ Wf, const float* __restrict__ bf,
       float* __restrict__ out)
{
    __shared__ float hs[4][512];
    __shared__ float Wt[32][129];
    __shared__ float xh_s[4][128];
    __shared__ float xc_s[4][128];
    __shared__ float wfdiag[128];
    const int tid = threadIdx.x;
    const int b0  = blockIdx.x << 2;

    if (tid < 128) wfdiag[tid] = Wf[tid*F_ + tid];

    // ---- Phase 1: LSTM carry update ----
    if (t == 0){
        for (int idx = tid; idx < 4*512; idx += 256){
            int b = idx >> 9, j = idx & 511;
            hs[b][j] = 0.f;
            g_c[(b0+b)*H_ + j] = 0.f;
            g_Ahi[(b0+b)*KG_ + 256 + j] = __float2bfloat16(0.f);
            g_Alo[(b0+b)*KG_ + 256 + j] = __float2bfloat16(0.f);
        }
    } else {
        for (int idx = tid; idx < 4*512; idx += 256){
            int b = idx >> 9, j = idx & 511;
            int gb = b0 + b;
            const float* grow = &g_gates[(size_t)gb*NG_];
            float ig = sigmoidf_(grow[j]);
            float fg = sigmoidf_(grow[512 + j]);
            float gg = tanhf    (grow[1024 + j]);
            float og = sigmoidf_(grow[1536 + j]);
            float c  = fg * g_c[gb*H_ + j] + ig*gg;
            g_c[gb*H_ + j] = c;
            float h  = og * tanhf(c);
            hs[b][j] = h;
            float hd = h * g_gammah[(size_t)(t*B_ + gb)*H_ + j];
            bsplit(hd, &g_Ahi[gb*KG_ + 256 + j], &g_Alo[gb*KG_ + 256 + j]);
        }
    }
    __syncthreads();

    const int n  = tid & 127;       // output feature
    const int hb = tid >> 7;        // 0/1 -> rows {hb*2, hb*2+1}

    // ---- Phase 2: x_h = h @ Wh^T + bh ----
    float acc[2] = {0.f, 0.f};
    for (int k0 = 0; k0 < H_; k0 += 32){
        for (int idx = tid; idx < 128*32; idx += 256){
            int nn = idx >> 5, kk = idx & 31;
            Wt[kk][nn] = Wh[nn*H_ + k0 + kk];
        }
        __syncthreads();
        #pragma unroll
        for (int k4 = 0; k4 < 8; k4++){
            float4 hv0 = *(const float4*)&hs[hb*2+0][k0 + k4*4];
            float4 hv1 = *(const float4*)&hs[hb*2+1][k0 + k4*4];
            #pragma unroll
            for (int c2 = 0; c2 < 4; c2++){
                float w = Wt[k4*4 + c2][n];
                acc[0] += w * ((&hv0.x)[c2]);
                acc[1] += w * ((&hv1.x)[c2]);
            }
        }
        __syncthreads();
    }

    float m_r[2], x_r[2];
    {
        float bhv = bh[n];
        #pragma unroll
        for (int i = 0; i < 2; i++){
            int b = hb*2 + i, gb = b0 + b;
            float xh = acc[i] + bhv;
            xh_s[b][n] = xh;
            int gi = gb*T_*F_ + t*F_ + n;
            float mv = (float)mask[gi];
            float xv = x[gi];
            m_r[i] = mv; x_r[i] = xv;
            xc_s[b][n] = mv*xv + (1.f - mv)*xh;
            out[3*BTF_ + gi] = xh;
        }
    }
    __syncthreads();

    // ---- Phase 3: z_h = x_c @ Wf^T (off-diag) + bf ----
    float acc2[2] = {0.f, 0.f};
    for (int k0 = 0; k0 < F_; k0 += 32){
        for (int idx = tid; idx < 128*32; idx += 256){
            int nn = idx >> 5, kk = idx & 31;
            Wt[kk][nn] = Wf[nn*F_ + k0 + kk];
        }
        __syncthreads();
        #pragma unroll
        for (int k4 = 0; k4 < 8; k4++){
            float4 v0 = *(const float4*)&xc_s[hb*2+0][k0 + k4*4];
            float4 v1 = *(const float4*)&xc_s[hb*2+1][k0 + k4*4];
            #pragma unroll
            for (int c2 = 0; c2 < 4; c2++){
                float w = Wt[k4*4 + c2][n];
                acc2[0] += w * ((&v0.x)[c2]);
                acc2[1] += w * ((&v1.x)[c2]);
            }
        }
        __syncthreads();
    }

    {
        float bfv = bf[n];
        #pragma unroll
        for (int i = 0; i < 2; i++){
            int b = hb*2 + i, gb = b0 + b;
            float z  = acc2[i] + bfv - xc_s[b][n]*wfdiag[n];   // off-diagonal mask
            float al = g_alpha[(size_t)(t*B_ + gb)*F_ + n];
            float xh = xh_s[b][n];
            float ch = al*z + (1.f - al)*xh;
            float cc = m_r[i]*x_r[i] + (1.f - m_r[i])*ch;
            int gi = gb*T_*F_ + t*F_ + n;
            out[gi]          = cc;   // imputation
            out[BTF_  + gi]  = ch;
            out[2*BTF_+ gi]  = z;
            bsplit(cc, &g_Ahi[gb*KG_ + n], &g_Alo[gb*KG_ + n]);
            g_Ahi[gb*KG_ + 128 + n] = __float2bfloat16(m_r[i]);
            g_Alo[gb*KG_ + 128 + n] = __float2bfloat16(0.f);
        }
    }
}

// ---------------- launch ----------------
extern "C" void kernel_launch(void* const* d_in, const int* in_sizes, int n_in,
                              void* d_out, int out_size)
{
    const float* x    = (const float*)d_in[0];
    const int*   mask = (const int*  )d_in[1];
    const float* Wdh  = (const float*)d_in[2];
    const float* bdh  = (const float*)d_in[3];
    const float* Wdx  = (const float*)d_in[4];
    const float* bdx  = (const float*)d_in[5];
    const float* Wh   = (const float*)d_in[6];
    const float* bh   = (const float*)d_in[7];
    const float* Wf   = (const float*)d_in[8];
    const float* bf   = (const float*)d_in[9];
    const float* Wc   = (const float*)d_in[10];
    const float* bc   = (const float*)d_in[11];
    const float* Wih  = (const float*)d_in[12];
    const float* Whh  = (const float*)d_in[13];
    const float* bih  = (const float*)d_in[14];
    const float* bhh  = (const float*)d_in[15];
    float* out = (float*)d_out;

    void *pDhi, *pDlo, *pA2hi, *pA2lo, *pAhi, *pAlo, *pWghi, *pWglo;
    void *pWdhhi, *pWdhlo, *pWchi, *pWclo;
    void *pGammah, *pAlpha, *pGates, *pBg;
    cudaGetSymbolAddress(&pDhi,    g_dhi);
    cudaGetSymbolAddress(&pDlo,    g_dlo);
    cudaGetSymbolAddress(&pA2hi,   g_A2hi);
    cudaGetSymbolAddress(&pA2lo,   g_A2lo);
    cudaGetSymbolAddress(&pAhi,    g_Ahi);
    cudaGetSymbolAddress(&pAlo,    g_Alo);
    cudaGetSymbolAddress(&pWghi,   g_Wghi);
    cudaGetSymbolAddress(&pWglo,   g_Wglo);
    cudaGetSymbolAddress(&pWdhhi,  g_Wdhhi);
    cudaGetSymbolAddress(&pWdhlo,  g_Wdhlo);
    cudaGetSymbolAddress(&pWchi,   g_Wchi);
    cudaGetSymbolAddress(&pWclo,   g_Wclo);
    cudaGetSymbolAddress(&pGammah, g_gammah);
    cudaGetSymbolAddress(&pAlpha,  g_alpha);
    cudaGetSymbolAddress(&pGates,  g_gates);
    cudaGetSymbolAddress(&pBg,     g_bg);

    // setup + time-parallel precomputes
    k_setup<<<2048, 256>>>(Wih, Whh, bih, bhh, Wdh, Wc);
    k_delta<<<256, 256>>>(mask);
    // gamma_h = exp(-relu(delta @ Wdh^T + bdh)) : [49152,128]@[128,512]
    gemm_sp<1><<<dim3(H_/128, TB_/64), 256>>>(
        (const __nv_bfloat16*)pDhi, (const __nv_bfloat16*)pDlo,
        (const __nv_bfloat16*)pWdhhi, (const __nv_bfloat16*)pWdhlo,
        bdh, (float*)pGammah, H_, F_);
    k_gx<<<(TB_*F_ + 255)/256, 256>>>(mask, Wdx, bdx);
    // alpha = sigmoid([gx,m] @ Wc^T + bc) : [49152,256]@[256,128]
    gemm_sp<2><<<dim3(F_/128, TB_/64), 256>>>(
        (const __nv_bfloat16*)pA2hi, (const __nv_bfloat16*)pA2lo,
        (const __nv_bfloat16*)pWchi, (const __nv_bfloat16*)pWclo,
        bc, (float*)pAlpha, F_, 2*F_);

    // sequential recurrence: 96 steps
    for (int t = 0; t < T_; t++){
        k_step<<<128, 256>>>(t, x, mask, Wh, bh, Wf, bf, out);
        if (t < T_ - 1){
            // gates = A @ Wg^T + bg : [512,768]@[768,2048]
            gemm_sp<0><<<dim3(NG_/128, B_/64), 256>>>(
                (const __nv_bfloat16*)pAhi, (const __nv_bfloat16*)pAlo,
                (const __nv_bfloat16*)pWghi, (const __nv_bfloat16*)pWglo,
                (const float*)pBg, (float*)pGates, NG_, KG_);
        }
    }
}

// round 9
// speedup vs baseline: 1.7159x; 1.0884x over previous
#include <cuda_runtime.h>
#include <cuda_bf16.h>
#include <cstdint>
#include <math.h>

#define B_ 512
#define T_ 96
#define F_ 128
#define H_ 512
#define TB_ (T_*B_)        // 49152
#define BTF_ (B_*T_*F_)    // 6291456
#define KG_ 768            // gates GEMM K = 2F + H
#define NG_ 2048           // 4H

typedef unsigned int u32;

// ---------------- scratch (device globals: no allocation allowed) ----------------
__device__ float g_delta[TB_*F_];
__device__ __align__(16) __nv_bfloat16 g_dhi[TB_*F_];
__device__ __align__(16) __nv_bfloat16 g_dlo[TB_*F_];
__device__ float g_gammah[TB_*H_];
__device__ __align__(16) __nv_bfloat16 g_A2hi[TB_*2*F_];
__device__ __align__(16) __nv_bfloat16 g_A2lo[TB_*2*F_];
__device__ float g_alpha[TB_*F_];
__device__ __align__(16) __nv_bfloat16 g_Ahi[B_*KG_];
__device__ __align__(16) __nv_bfloat16 g_Alo[B_*KG_];
__device__ float g_gates[B_*NG_];
__device__ float g_c[B_*H_];
__device__ __align__(16) __nv_bfloat16 g_Wghi[NG_*KG_];
__device__ __align__(16) __nv_bfloat16 g_Wglo[NG_*KG_];
__device__ float g_bg[NG_];
__device__ __align__(16) __nv_bfloat16 g_Wdhhi[H_*F_];
__device__ __align__(16) __nv_bfloat16 g_Wdhlo[H_*F_];
__device__ __align__(16) __nv_bfloat16 g_Wchi[F_*2*F_];
__device__ __align__(16) __nv_bfloat16 g_Wclo[F_*2*F_];

__device__ __forceinline__ float sigmoidf_(float v){ return 1.f/(1.f+expf(-v)); }

__device__ __forceinline__ void bsplit(float v, __nv_bfloat16* hi, __nv_bfloat16* lo){
    __nv_bfloat16 h = __float2bfloat16(v);
    *hi = h;
    *lo = __float2bfloat16(v - __bfloat162float(h));
}

__device__ __forceinline__ u32 sptr(const void* p){
    return (u32)__cvta_generic_to_shared(p);
}

__device__ __forceinline__ void ldsm4(u32* r, u32 addr){
    asm volatile("ldmatrix.sync.aligned.m8n8.x4.shared.b16 {%0,%1,%2,%3}, [%4];"
        : "=r"(r[0]),"=r"(r[1]),"=r"(r[2]),"=r"(r[3]) : "r"(addr));
}

__device__ __forceinline__ void mma16816(float* c, const u32* a, u32 b0, u32 b1){
    asm volatile("mma.sync.aligned.m16n8k16.row.col.f32.bf16.bf16.f32 "
        "{%0,%1,%2,%3},{%4,%5,%6,%7},{%8,%9},{%0,%1,%2,%3};"
        : "+f"(c[0]),"+f"(c[1]),"+f"(c[2]),"+f"(c[3])
        : "r"(a[0]),"r"(a[1]),"r"(a[2]),"r"(a[3]), "r"(b0),"r"(b1));
}

__device__ __forceinline__ void cpasync16(u32 dst, const void* src){
    asm volatile("cp.async.cg.shared.global [%0], [%1], 16;" :: "r"(dst), "l"(src));
}

// ---------------- setup: fuse + split all weights ----------------
__global__ void k_setup(const float* __restrict__ Wih, const float* __restrict__ Whh,
                        const float* __restrict__ bih, const float* __restrict__ bhh,
                        const float* __restrict__ Wdh, const float* __restrict__ Wc){
    int tid0 = blockIdx.x*blockDim.x + threadIdx.x;
    int stride = gridDim.x*blockDim.x;
    for (int idx = tid0; idx < NG_*KG_; idx += stride){
        int n = idx / KG_;
        int k = idx - n*KG_;
        float v = (k < 256) ? Wih[n*256 + k] : Whh[n*H_ + (k-256)];
        bsplit(v, &g_Wghi[idx], &g_Wglo[idx]);
    }
    for (int idx = tid0; idx < H_*F_; idx += stride)
        bsplit(Wdh[idx], &g_Wdhhi[idx], &g_Wdhlo[idx]);
    for (int idx = tid0; idx < F_*2*F_; idx += stride)
        bsplit(Wc[idx], &g_Wchi[idx], &g_Wclo[idx]);
    if (tid0 < NG_) g_bg[tid0] = bih[tid0] + bhh[tid0];
}

// ---------------- delta scan ----------------
__global__ void k_delta(const int* __restrict__ mask){
    int idx = blockIdx.x*blockDim.x + threadIdx.x;
    int b = idx >> 7, f = idx & 127;
    const int base = b*T_*F_ + f;
    float d = 0.f;
    #pragma unroll 4
    for (int t = 0; t < T_; t++){
        int o = t*B_*F_ + b*F_ + f;
        g_delta[o] = d;
        bsplit(d, &g_dhi[o], &g_dlo[o]);
        float mp = (float)mask[base + t*F_];
        d = mp + (1.f - mp)*(d + 1.f);
    }
}

// ---------------- gamma_x + alpha-input assembly ----------------
__global__ void k_gx(const int* __restrict__ mask, const float* __restrict__ Wdx,
                     const float* __restrict__ bdx){
    int idx = blockIdx.x*blockDim.x + threadIdx.x;
    if (idx >= TB_*F_) return;
    int r = idx >> 7, f = idx & 127;
    int t = r / B_, b = r - t*B_;
    float d  = g_delta[idx];
    float gx = expf(-fmaxf(d * Wdx[f*F_ + f] + bdx[f], 0.f));
    bsplit(gx, &g_A2hi[r*256 + f], &g_A2lo[r*256 + f]);
    float mv = (float)mask[b*T_*F_ + t*F_ + f];
    g_A2hi[r*256 + 128 + f] = __float2bfloat16(mv);
    g_A2lo[r*256 + 128 + f] = __float2bfloat16(0.f);
}

// ---------------- fused split-bf16 mma.sync GEMM, cp.async double-buffered ------
// C[M,N] = (Ahi+Alo)[M,K] @ (Whi+Wlo)[N,K]^T + bias
// Fused 3-term: hi*hi + lo*hi + hi*lo in ONE K loop (4 tiles staged per chunk).
// CTA tile 64(M) x 128(N), K chunk 64, 256 threads = 8 warps (2M x 4N), warp 32x32.
// EPI: 0 none, 1 exp(-relu(v)), 2 sigmoid(v). M%64==0, N%128==0, K%64==0.
#define SSTR 72                        // padded smem row stride (bf16): 144B
#define ROWS_PB 384                    // 64+64+128+128 rows per buffer
#define BUFSZ (ROWS_PB*SSTR)           // bf16 elems per buffer
#define GF_SMEM (2*BUFSZ*2)            // bytes: 110592

template<int EPI>
__global__ void __launch_bounds__(256, 1)
gemm_fu(const __nv_bfloat16* __restrict__ Ahi, const __nv_bfloat16* __restrict__ Alo,
        const __nv_bfloat16* __restrict__ Whi, const __nv_bfloat16* __restrict__ Wlo,
        const float* __restrict__ bias, float* __restrict__ C, int N, int K)
{
    extern __shared__ __align__(16) __nv_bfloat16 smbuf[];
    const int tid = threadIdx.x, lane = tid & 31, wid = tid >> 5;
    const int m0 = blockIdx.y*64, n0 = blockIdx.x*128;
    const int wm = (wid & 1)*32, wn = (wid >> 1)*32;
    const int NC = K >> 6;

    float acc[2][4][4];
    #pragma unroll
    for (int i=0;i<2;i++)
        #pragma unroll
        for (int j=0;j<4;j++)
            #pragma unroll
            for (int q=0;q<4;q++) acc[i][j][q] = 0.f;

    const int aRow = lane & 15;
    const int aCol = ((lane >> 4) & 1) * 8;
    const int bRow = (lane & 7) + ((lane >> 4) & 1) * 8;
    const int bCol = ((lane >> 3) & 1) * 8;

    // per-thread staging map: 12 x 16B chunks; r in [0,384)
    int s_r[12], s_row[12];
    const __nv_bfloat16* s_src[12];
    #pragma unroll
    for (int j = 0; j < 12; j++){
        int u = tid + j*256;
        int r = u >> 3;
        s_r[j] = u;
        if (r < 64)      { s_src[j] = Ahi; s_row[j] = m0 + r; }
        else if (r < 128){ s_src[j] = Alo; s_row[j] = m0 + r - 64; }
        else if (r < 256){ s_src[j] = Whi; s_row[j] = n0 + r - 128; }
        else             { s_src[j] = Wlo; s_row[j] = n0 + r - 256; }
    }

    // ---- stage chunk 0 ----
    {
        __nv_bfloat16* tb = smbuf;
        #pragma unroll
        for (int j = 0; j < 12; j++){
            int u = s_r[j]; int r = u >> 3, c = (u & 7)*8;
            cpasync16(sptr(&tb[r*SSTR + c]), &s_src[j][(size_t)s_row[j]*K + c]);
        }
        asm volatile("cp.async.commit_group;" ::: "memory");
    }

    for (int ch = 0; ch < NC; ch++){
        if (ch + 1 < NC){
            __nv_bfloat16* tb = smbuf + ((ch+1)&1)*BUFSZ;
            const int k1 = (ch+1)*64;
            #pragma unroll
            for (int j = 0; j < 12; j++){
                int u = s_r[j]; int r = u >> 3, c = (u & 7)*8;
                cpasync16(sptr(&tb[r*SSTR + c]), &s_src[j][(size_t)s_row[j]*K + k1 + c]);
            }
            asm volatile("cp.async.commit_group;" ::: "memory");
            asm volatile("cp.async.wait_group 1;" ::: "memory");
        } else {
            asm volatile("cp.async.wait_group 0;" ::: "memory");
        }
        __syncthreads();

        const __nv_bfloat16* bb = smbuf + (ch&1)*BUFSZ;
        const __nv_bfloat16* As_hi = bb;
        const __nv_bfloat16* As_lo = bb + 64*SSTR;
        const __nv_bfloat16* Ws_hi = bb + 128*SSTR;
        const __nv_bfloat16* Ws_lo = bb + 256*SSTR;

        #pragma unroll
        for (int kk = 0; kk < 64; kk += 16){
            u32 ah[2][4], al[2][4], bh[2][4], bl[2][4];
            #pragma unroll
            for (int mt = 0; mt < 2; mt++){
                ldsm4(ah[mt], sptr(&As_hi[(wm + mt*16 + aRow)*SSTR + kk + aCol]));
                ldsm4(al[mt], sptr(&As_lo[(wm + mt*16 + aRow)*SSTR + kk + aCol]));
            }
            #pragma unroll
            for (int nt = 0; nt < 2; nt++){
                ldsm4(bh[nt], sptr(&Ws_hi[(wn + nt*16 + bRow)*SSTR + kk + bCol]));
                ldsm4(bl[nt], sptr(&Ws_lo[(wn + nt*16 + bRow)*SSTR + kk + bCol]));
            }
            #pragma unroll
            for (int mt = 0; mt < 2; mt++)
                #pragma unroll
                for (int nj = 0; nj < 4; nj++){
                    const u32* ph = &bh[nj >> 1][(nj & 1) * 2];
                    const u32* pl = &bl[nj >> 1][(nj & 1) * 2];
                    mma16816(acc[mt][nj], ah[mt], ph[0], ph[1]);   // hi*hi
                    mma16816(acc[mt][nj], al[mt], ph[0], ph[1]);   // lo*hi
                    mma16816(acc[mt][nj], ah[mt], pl[0], pl[1]);   // hi*lo
                }
        }
        __syncthreads();
    }

    #pragma unroll
    for (int mt = 0; mt < 2; mt++){
        int row = m0 + wm + mt*16 + (lane >> 2);
        #pragma unroll
        for (int nj = 0; nj < 4; nj++){
            int col = n0 + wn + nj*8 + (lane & 3)*2;
            float b0v = bias[col], b1v = bias[col+1];
            float v[4] = { acc[mt][nj][0] + b0v, acc[mt][nj][1] + b1v,
                           acc[mt][nj][2] + b0v, acc[mt][nj][3] + b1v };
            #pragma unroll
            for (int q = 0; q < 4; q++){
                if (EPI == 1)      v[q] = expf(-fmaxf(v[q], 0.f));
                else if (EPI == 2) v[q] = 1.f/(1.f+expf(-v[q]));
            }
            C[(size_t)row*N + col]         = v[0];
            C[(size_t)row*N + col + 1]     = v[1];
            C[(size_t)(row+8)*N + col]     = v[2];
            C[(size_t)(row+8)*N + col + 1] = v[3];
        }
    }
}

// ---------------- per-step fused kernel ----------------
__global__ void __launch_bounds__(256)
k_step(int t, const float* __restrict__ x, const int* __restrict__ mask,
       const float* __restrict__ Wh, const float* __restrict__ bh,
       const float* __restrict__ Wf, const float* __restrict__ bf,
       float* __restrict__ out)
{
    __shared__ float hs[4][512];
    __shared__ float Wt[32][129];
    __shared__ float xh_s[4][128];
    __shared__ float xc_s[4][128];
    __shared__ float wfdiag[128];
    const int tid = threadIdx.x;
    const int b0  = blockIdx.x << 2;

    if (tid < 128) wfdiag[tid] = Wf[tid*F_ + tid];

    if (t == 0){
        for (int idx = tid; idx < 4*512; idx += 256){
            int b = idx >> 9, j = idx & 511;
            hs[b][j] = 0.f;
            g_c[(b0+b)*H_ + j] = 0.f;
            g_Ahi[(b0+b)*KG_ + 256 + j] = __float2bfloat16(0.f);
            g_Alo[(b0+b)*KG_ + 256 + j] = __float2bfloat16(0.f);
        }
    } else {
        for (int idx = tid; idx < 4*512; idx += 256){
            int b = idx >> 9, j = idx & 511;
            int gb = b0 + b;
            const float* grow = &g_gates[(size_t)gb*NG_];
            float ig = sigmoidf_(grow[j]);
            float fg = sigmoidf_(grow[512 + j]);
            float gg = tanhf    (grow[1024 + j]);
            float og = sigmoidf_(grow[1536 + j]);
            float c  = fg * g_c[gb*H_ + j] + ig*gg;
            g_c[gb*H_ + j] = c;
            float h  = og * tanhf(c);
            hs[b][j] = h;
            float hd = h * g_gammah[(size_t)(t*B_ + gb)*H_ + j];
            bsplit(hd, &g_Ahi[gb*KG_ + 256 + j], &g_Alo[gb*KG_ + 256 + j]);
        }
    }
    __syncthreads();

    const int n  = tid & 127;
    const int hb = tid >> 7;

    float acc[2] = {0.f, 0.f};
    for (int k0 = 0; k0 < H_; k0 += 32){
        for (int idx = tid; idx < 128*32; idx += 256){
            int nn = idx >> 5, kk = idx & 31;
            Wt[kk][nn] = Wh[nn*H_ + k0 + kk];
        }
        __syncthreads();
        #pragma unroll
        for (int k4 = 0; k4 < 8; k4++){
            float4 hv0 = *(const float4*)&hs[hb*2+0][k0 + k4*4];
            float4 hv1 = *(const float4*)&hs[hb*2+1][k0 + k4*4];
            #pragma unroll
            for (int c2 = 0; c2 < 4; c2++){
                float w = Wt[k4*4 + c2][n];
                acc[0] += w * ((&hv0.x)[c2]);
                acc[1] += w * ((&hv1.x)[c2]);
            }
        }
        __syncthreads();
    }

    float m_r[2], x_r[2];
    {
        float bhv = bh[n];
        #pragma unroll
        for (int i = 0; i < 2; i++){
            int b = hb*2 + i, gb = b0 + b;
            float xh = acc[i] + bhv;
            xh_s[b][n] = xh;
            int gi = gb*T_*F_ + t*F_ + n;
            float mv = (float)mask[gi];
            float xv = x[gi];
            m_r[i] = mv; x_r[i] = xv;
            xc_s[b][n] = mv*xv + (1.f - mv)*xh;
            out[3*BTF_ + gi] = xh;
        }
    }
    __syncthreads();

    float acc2[2] = {0.f, 0.f};
    for (int k0 = 0; k0 < F_; k0 += 32){
        for (int idx = tid; idx < 128*32; idx += 256){
            int nn = idx >> 5, kk = idx & 31;
            Wt[kk][nn] = Wf[nn*F_ + k0 + kk];
        }
        __syncthreads();
        #pragma unroll
        for (int k4 = 0; k4 < 8; k4++){
            float4 v0 = *(const float4*)&xc_s[hb*2+0][k0 + k4*4];
            float4 v1 = *(const float4*)&xc_s[hb*2+1][k0 + k4*4];
            #pragma unroll
            for (int c2 = 0; c2 < 4; c2++){
                float w = Wt[k4*4 + c2][n];
                acc2[0] += w * ((&v0.x)[c2]);
                acc2[1] += w * ((&v1.x)[c2]);
            }
        }
        __syncthreads();
    }

    {
        float bfv = bf[n];
        #pragma unroll
        for (int i = 0; i < 2; i++){
            int b = hb*2 + i, gb = b0 + b;
            float z  = acc2[i] + bfv - xc_s[b][n]*wfdiag[n];
            float al = g_alpha[(size_t)(t*B_ + gb)*F_ + n];
            float xh = xh_s[b][n];
            float ch = al*z + (1.f - al)*xh;
            float cc = m_r[i]*x_r[i] + (1.f - m_r[i])*ch;
            int gi = gb*T_*F_ + t*F_ + n;
            out[gi]          = cc;
            out[BTF_  + gi]  = ch;
            out[2*BTF_+ gi]  = z;
            bsplit(cc, &g_Ahi[gb*KG_ + n], &g_Alo[gb*KG_ + n]);
            g_Ahi[gb*KG_ + 128 + n] = __float2bfloat16(m_r[i]);
            g_Alo[gb*KG_ + 128 + n] = __float2bfloat16(0.f);
        }
    }
}

// ---------------- launch ----------------
extern "C" void kernel_launch(void* const* d_in, const int* in_sizes, int n_in,
                              void* d_out, int out_size)
{
    const float* x    = (const float*)d_in[0];
    const int*   mask = (const int*  )d_in[1];
    const float* Wdh  = (const float*)d_in[2];
    const float* bdh  = (const float*)d_in[3];
    const float* Wdx  = (const float*)d_in[4];
    const float* bdx  = (const float*)d_in[5];
    const float* Wh   = (const float*)d_in[6];
    const float* bh   = (const float*)d_in[7];
    const float* Wf   = (const float*)d_in[8];
    const float* bf   = (const float*)d_in[9];
    const float* Wc   = (const float*)d_in[10];
    const float* bc   = (const float*)d_in[11];
    const float* Wih  = (const float*)d_in[12];
    const float* Whh  = (const float*)d_in[13];
    const float* bih  = (const float*)d_in[14];
    const float* bhh  = (const float*)d_in[15];
    float* out = (float*)d_out;

    void *pDhi, *pDlo, *pA2hi, *pA2lo, *pAhi, *pAlo, *pWghi, *pWglo;
    void *pWdhhi, *pWdhlo, *pWchi, *pWclo;
    void *pGammah, *pAlpha, *pGates, *pBg;
    cudaGetSymbolAddress(&pDhi,    g_dhi);
    cudaGetSymbolAddress(&pDlo,    g_dlo);
    cudaGetSymbolAddress(&pA2hi,   g_A2hi);
    cudaGetSymbolAddress(&pA2lo,   g_A2lo);
    cudaGetSymbolAddress(&pAhi,    g_Ahi);
    cudaGetSymbolAddress(&pAlo,    g_Alo);
    cudaGetSymbolAddress(&pWghi,   g_Wghi);
    cudaGetSymbolAddress(&pWglo,   g_Wglo);
    cudaGetSymbolAddress(&pWdhhi,  g_Wdhhi);
    cudaGetSymbolAddress(&pWdhlo,  g_Wdhlo);
    cudaGetSymbolAddress(&pWchi,   g_Wchi);
    cudaGetSymbolAddress(&pWclo,   g_Wclo);
    cudaGetSymbolAddress(&pGammah, g_gammah);
    cudaGetSymbolAddress(&pAlpha,  g_alpha);
    cudaGetSymbolAddress(&pGates,  g_gates);
    cudaGetSymbolAddress(&pBg,     g_bg);

    cudaFuncSetAttribute(gemm_fu<0>, cudaFuncAttributeMaxDynamicSharedMemorySize, GF_SMEM);
    cudaFuncSetAttribute(gemm_fu<1>, cudaFuncAttributeMaxDynamicSharedMemorySize, GF_SMEM);
    cudaFuncSetAttribute(gemm_fu<2>, cudaFuncAttributeMaxDynamicSharedMemorySize, GF_SMEM);

    // setup + time-parallel precomputes
    k_setup<<<2048, 256>>>(Wih, Whh, bih, bhh, Wdh, Wc);
    k_delta<<<256, 256>>>(mask);
    // gamma_h = exp(-relu(delta @ Wdh^T + bdh)) : [49152,128]@[128,512]
    gemm_fu<1><<<dim3(H_/128, TB_/64), 256, GF_SMEM>>>(
        (const __nv_bfloat16*)pDhi, (const __nv_bfloat16*)pDlo,
        (const __nv_bfloat16*)pWdhhi, (const __nv_bfloat16*)pWdhlo,
        bdh, (float*)pGammah, H_, F_);
    k_gx<<<(TB_*F_ + 255)/256, 256>>>(mask, Wdx, bdx);
    // alpha = sigmoid([gx,m] @ Wc^T + bc) : [49152,256]@[256,128]
    gemm_fu<2><<<dim3(F_/128, TB_/64), 256, GF_SMEM>>>(
        (const __nv_bfloat16*)pA2hi, (const __nv_bfloat16*)pA2lo,
        (const __nv_bfloat16*)pWchi, (const __nv_bfloat16*)pWclo,
        bc, (float*)pAlpha, F_, 2*F_);

    // sequential recurrence: 96 steps
    for (int t = 0; t < T_; t++){
        k_step<<<128, 256>>>(t, x, mask, Wh, bh, Wf, bf, out);
        if (t < T_ - 1){
            // gates = A @ Wg^T + bg : [512,768]@[768,2048]
            gemm_fu<0><<<dim3(NG_/128, B_/64), 256, GF_SMEM>>>(
                (const __nv_bfloat16*)pAhi, (const __nv_bfloat16*)pAlo,
                (const __nv_bfloat16*)pWghi, (const __nv_bfloat16*)pWglo,
                (const float*)pBg, (float*)pGates, NG_, KG_);
        }
    }
}

// round 10
// speedup vs baseline: 2.4980x; 1.4558x over previous
#include <cuda_runtime.h>
#include <cuda_fp16.h>
#include <cstdint>
#include <math.h>

#define B_ 512
#define T_ 96
#define F_ 128
#define H_ 512
#define TB_ (T_*B_)        // 49152
#define BTF_ (B_*T_*F_)    // 6291456
#define KG_ 768            // gates GEMM K = 2F + H
#define NG_ 2048           // 4H

typedef unsigned int u32;

// ---------------- scratch (device globals: no allocation allowed) ----------------
__device__ __align__(16) __half g_d16[TB_*F_];     // delta (integer-valued, fp16 exact)
__device__ float g_gammah[TB_*H_];                 // [t*B+b, h]
__device__ __align__(16) __half g_A216[TB_*2*F_];  // [t*B+b, gx|m]
__device__ float g_alpha[TB_*F_];
__device__ __align__(16) __half g_A16[B_*KG_];     // per-step A = [c_c | m | h*gamma]
__device__ float g_c[B_*H_];
__device__ float g_h[B_*H_];
__device__ __align__(16) __half g_Wg16[NG_*KG_];   // [Wih|Whh] fused, gate-interleaved
__device__ float g_bgR[NG_];                       // bih+bhh, gate-interleaved
__device__ __align__(16) __half g_Wdh16[H_*F_];
__device__ __align__(16) __half g_WdhR[H_*F_];     // (W - fp16(W))*1024
__device__ __align__(16) __half g_Wc16[F_*2*F_];
__device__ __align__(16) __half g_WcR[F_*2*F_];

__device__ __forceinline__ float sigmoidf_(float v){ return 1.f/(1.f+expf(-v)); }

__device__ __forceinline__ u32 sptr(const void* p){
    return (u32)__cvta_generic_to_shared(p);
}

__device__ __forceinline__ void ldsm4(u32* r, u32 addr){
    asm volatile("ldmatrix.sync.aligned.m8n8.x4.shared.b16 {%0,%1,%2,%3}, [%4];"
        : "=r"(r[0]),"=r"(r[1]),"=r"(r[2]),"=r"(r[3]) : "r"(addr));
}

// fp16 inputs, fp32 accumulate
__device__ __forceinline__ void mma16816h(float* c, const u32* a, u32 b0, u32 b1){
    asm volatile("mma.sync.aligned.m16n8k16.row.col.f32.f16.f16.f32 "
        "{%0,%1,%2,%3},{%4,%5,%6,%7},{%8,%9},{%0,%1,%2,%3};"
        : "+f"(c[0]),"+f"(c[1]),"+f"(c[2]),"+f"(c[3])
        : "r"(a[0]),"r"(a[1]),"r"(a[2]),"r"(a[3]), "r"(b0),"r"(b1));
}

__device__ __forceinline__ void cpasync16(u32 dst, const void* src){
    asm volatile("cp.async.cg.shared.global [%0], [%1], 16;" :: "r"(dst), "l"(src));
}

// ---------------- setup: reorder/split weights + zero state ----------------
__global__ void k_setup(const float* __restrict__ Wih, const float* __restrict__ Whh,
                        const float* __restrict__ bih, const float* __restrict__ bhh,
                        const float* __restrict__ Wdh, const float* __restrict__ Wc){
    int tid0 = blockIdx.x*blockDim.x + threadIdx.x;
    int stride = gridDim.x*blockDim.x;
    // Wg: col n' = 4*j + gate, gate order (i,f,g,o) <- old row g*512 + j
    for (int idx = tid0; idx < NG_*KG_; idx += stride){
        int n = idx / KG_;
        int k = idx - n*KG_;
        int j = n >> 2, g = n & 3;
        int no = g*512 + j;
        float v = (k < 256) ? Wih[no*256 + k] : Whh[no*H_ + (k-256)];
        g_Wg16[idx] = __float2half(v);
    }
    for (int idx = tid0; idx < H_*F_; idx += stride){
        float v = Wdh[idx];
        __half h = __float2half(v);
        g_Wdh16[idx] = h;
        g_WdhR[idx]  = __float2half((v - __half2float(h))*1024.f);
    }
    for (int idx = tid0; idx < F_*2*F_; idx += stride){
        float v = Wc[idx];
        __half h = __float2half(v);
        g_Wc16[idx] = h;
        g_WcR[idx]  = __float2half((v - __half2float(h))*1024.f);
    }
    for (int idx = tid0; idx < B_*H_; idx += stride){
        g_c[idx] = 0.f;
        g_h[idx] = 0.f;
        g_A16[(idx >> 9)*KG_ + 256 + (idx & 511)] = __float2half(0.f);  // hγ slice
    }
    if (tid0 < NG_){
        int j = tid0 >> 2, g = tid0 & 3;
        int no = g*512 + j;
        g_bgR[tid0] = bih[no] + bhh[no];
    }
}

// ---------------- delta scan + gamma_x + alpha-input (fused) ----------------
__global__ void k_delta2(const int* __restrict__ mask, const float* __restrict__ Wdx,
                         const float* __restrict__ bdx){
    int idx = blockIdx.x*blockDim.x + threadIdx.x;   // B*F = 65536
    int b = idx >> 7, f = idx & 127;
    const float wdx = Wdx[f*F_ + f];
    const float bx  = bdx[f];
    const int base = b*T_*F_ + f;
    float d = 0.f;
    for (int t = 0; t < T_; t++){
        int o = t*B_ + b;
        g_d16[o*F_ + f] = __float2half(d);   // integer, exact
        float gx = expf(-fmaxf(d*wdx + bx, 0.f));
        float mp = (float)mask[base + t*F_];
        g_A216[o*256 + f]       = __float2half(gx);
        g_A216[o*256 + 128 + f] = __float2half(mp);
        d = mp + (1.f - mp)*(d + 1.f);
    }
}

// ---------------- 2-pass fp16 GEMM (precompute): C = A@(W + Wr/1024)^T + bias --
// CTA 64(M) x 128(N), K chunk 64, 8 warps (2Mx4N), warp 32x32. cp.async 2-buf.
#define SSTR 72
#define R2P 320                    // 64 A + 128 W + 128 Wr rows
#define B2P (R2P*SSTR)             // halfs per buffer
#define SM2P (2*B2P*2)             // 92160 bytes

template<int EPI>   // 1: exp(-relu), 2: sigmoid
__global__ void __launch_bounds__(256, 1)
gemm_2p(const __half* __restrict__ A, const __half* __restrict__ W,
        const __half* __restrict__ Wr, const float* __restrict__ bias,
        float* __restrict__ C, int N, int K)
{
    extern __shared__ __align__(16) __half smh[];
    const int tid = threadIdx.x, lane = tid & 31, wid = tid >> 5;
    const int m0 = blockIdx.y*64, n0 = blockIdx.x*128;
    const int wm = (wid & 1)*32, wn = (wid >> 1)*32;
    const int NC = K >> 6;

    float acc1[2][4][4], acc2[2][4][4];
    #pragma unroll
    for (int i=0;i<2;i++)
        #pragma unroll
        for (int j=0;j<4;j++)
            #pragma unroll
            for (int q=0;q<4;q++){ acc1[i][j][q]=0.f; acc2[i][j][q]=0.f; }

    const int aRow = lane & 15;
    const int aCol = ((lane >> 4) & 1) * 8;
    const int bRow = (lane & 7) + ((lane >> 4) & 1) * 8;
    const int bCol = ((lane >> 3) & 1) * 8;

    const __half* s_src[10]; int s_row[10];
    #pragma unroll
    for (int j = 0; j < 10; j++){
        int u = tid + j*256; int r = u >> 3;
        if (r < 64)      { s_src[j] = A;  s_row[j] = m0 + r; }
        else if (r < 192){ s_src[j] = W;  s_row[j] = n0 + r - 64; }
        else             { s_src[j] = Wr; s_row[j] = n0 + r - 192; }
    }

    {
        #pragma unroll
        for (int j = 0; j < 10; j++){
            int u = tid + j*256; int r = u >> 3, c = (u & 7)*8;
            cpasync16(sptr(&smh[r*SSTR + c]), &s_src[j][(size_t)s_row[j]*K + c]);
        }
        asm volatile("cp.async.commit_group;" ::: "memory");
    }

    for (int ch = 0; ch < NC; ch++){
        if (ch + 1 < NC){
            __half* tb = smh + ((ch+1)&1)*B2P;
            const int k1 = (ch+1)*64;
            #pragma unroll
            for (int j = 0; j < 10; j++){
                int u = tid + j*256; int r = u >> 3, c = (u & 7)*8;
                cpasync16(sptr(&tb[r*SSTR + c]), &s_src[j][(size_t)s_row[j]*K + k1 + c]);
            }
            asm volatile("cp.async.commit_group;" ::: "memory");
            asm volatile("cp.async.wait_group 1;" ::: "memory");
        } else {
            asm volatile("cp.async.wait_group 0;" ::: "memory");
        }
        __syncthreads();

        const __half* bb = smh + (ch&1)*B2P;
        const __half* As = bb;
        const __half* Ws = bb + 64*SSTR;
        const __half* Rs = bb + 192*SSTR;

        #pragma unroll
        for (int kk = 0; kk < 64; kk += 16){
            u32 a[2][4], bw[2][4], br[2][4];
            #pragma unroll
            for (int mt = 0; mt < 2; mt++)
                ldsm4(a[mt], sptr(&As[(wm + mt*16 + aRow)*SSTR + kk + aCol]));
            #pragma unroll
            for (int nt = 0; nt < 2; nt++){
                ldsm4(bw[nt], sptr(&Ws[(wn + nt*16 + bRow)*SSTR + kk + bCol]));
                ldsm4(br[nt], sptr(&Rs[(wn + nt*16 + bRow)*SSTR + kk + bCol]));
            }
            #pragma unroll
            for (int mt = 0; mt < 2; mt++)
                #pragma unroll
                for (int nj = 0; nj < 4; nj++){
                    const u32* pw = &bw[nj >> 1][(nj & 1) * 2];
                    const u32* pr = &br[nj >> 1][(nj & 1) * 2];
                    mma16816h(acc1[mt][nj], a[mt], pw[0], pw[1]);
                    mma16816h(acc2[mt][nj], a[mt], pr[0], pr[1]);
                }
        }
        __syncthreads();
    }

    const float rs = 1.f/1024.f;
    #pragma unroll
    for (int mt = 0; mt < 2; mt++){
        int row = m0 + wm + mt*16 + (lane >> 2);
        #pragma unroll
        for (int nj = 0; nj < 4; nj++){
            int col = n0 + wn + nj*8 + (lane & 3)*2;
            float b0v = bias[col], b1v = bias[col+1];
            float v[4] = { acc1[mt][nj][0] + acc2[mt][nj][0]*rs + b0v,
                           acc1[mt][nj][1] + acc2[mt][nj][1]*rs + b1v,
                           acc1[mt][nj][2] + acc2[mt][nj][2]*rs + b0v,
                           acc1[mt][nj][3] + acc2[mt][nj][3]*rs + b1v };
            #pragma unroll
            for (int q = 0; q < 4; q++){
                if (EPI == 1)      v[q] = expf(-fmaxf(v[q], 0.f));
                else if (EPI == 2) v[q] = 1.f/(1.f+expf(-v[q]));
            }
            C[(size_t)row*N + col]         = v[0];
            C[(size_t)row*N + col + 1]     = v[1];
            C[(size_t)(row+8)*N + col]     = v[2];
            C[(size_t)(row+8)*N + col + 1] = v[3];
        }
    }
}

// ---------------- gates GEMM (1-pass fp16) + fused LSTM epilogue ----------------
// A[512,768]@Wg16[2048,768]^T + bg -> gates (gate-interleaved cols: 4j+{i,f,g,o}).
// Epilogue: per CTA (64 batches x 32 units): LSTM update -> c, h, h*gamma(t+1) into A16.
// CTA 64(M) x 128(N), grid (16, 8) = 128 CTAs.
#define RG 192                     // 64 A + 128 W rows
#define BG (RG*SSTR)
#define SMG (2*BG*2)               // 55296 bytes (Cs 32KB overlays buffer after mainloop)

__global__ void __launch_bounds__(256, 1)
gemm_g(const __half* __restrict__ A, const __half* __restrict__ W,
       const float* __restrict__ bias, int t)
{
    extern __shared__ __align__(16) __half smh[];
    const int tid = threadIdx.x, lane = tid & 31, wid = tid >> 5;
    const int m0 = blockIdx.y*64, n0 = blockIdx.x*128;
    const int wm = (wid & 1)*32, wn = (wid >> 1)*32;
    const int NC = KG_ >> 6;   // 12

    float acc[2][4][4];
    #pragma unroll
    for (int i=0;i<2;i++)
        #pragma unroll
        for (int j=0;j<4;j++)
            #pragma unroll
            for (int q=0;q<4;q++) acc[i][j][q] = 0.f;

    const int aRow = lane & 15;
    const int aCol = ((lane >> 4) & 1) * 8;
    const int bRow = (lane & 7) + ((lane >> 4) & 1) * 8;
    const int bCol = ((lane >> 3) & 1) * 8;

    const __half* s_src[6]; int s_row[6];
    #pragma unroll
    for (int j = 0; j < 6; j++){
        int u = tid + j*256; int r = u >> 3;
        if (r < 64){ s_src[j] = A; s_row[j] = m0 + r; }
        else       { s_src[j] = W; s_row[j] = n0 + r - 64; }
    }

    {
        #pragma unroll
        for (int j = 0; j < 6; j++){
            int u = tid + j*256; int r = u >> 3, c = (u & 7)*8;
            cpasync16(sptr(&smh[r*SSTR + c]), &s_src[j][(size_t)s_row[j]*KG_ + c]);
        }
        asm volatile("cp.async.commit_group;" ::: "memory");
    }

    for (int ch = 0; ch < NC; ch++){
        if (ch + 1 < NC){
            __half* tb = smh + ((ch+1)&1)*BG;
            const int k1 = (ch+1)*64;
            #pragma unroll
            for (int j = 0; j < 6; j++){
                int u = tid + j*256; int r = u >> 3, c = (u & 7)*8;
                cpasync16(sptr(&tb[r*SSTR + c]), &s_src[j][(size_t)s_row[j]*KG_ + k1 + c]);
            }
            asm volatile("cp.async.commit_group;" ::: "memory");
            asm volatile("cp.async.wait_group 1;" ::: "memory");
        } else {
            asm volatile("cp.async.wait_group 0;" ::: "memory");
        }
        __syncthreads();

        const __half* bb = smh + (ch&1)*BG;
        const __half* As = bb;
        const __half* Ws = bb + 64*SSTR;

        #pragma unroll
        for (int kk = 0; kk < 64; kk += 16){
            u32 a[2][4], b[2][4];
            #pragma unroll
            for (int mt = 0; mt < 2; mt++)
                ldsm4(a[mt], sptr(&As[(wm + mt*16 + aRow)*SSTR + kk + aCol]));
            #pragma unroll
            for (int nt = 0; nt < 2; nt++)
                ldsm4(b[nt], sptr(&Ws[(wn + nt*16 + bRow)*SSTR + kk + bCol]));
            #pragma unroll
            for (int mt = 0; mt < 2; mt++)
                #pragma unroll
                for (int nj = 0; nj < 4; nj++){
                    const u32* pb = &b[nj >> 1][(nj & 1) * 2];
                    mma16816h(acc[mt][nj], a[mt], pb[0], pb[1]);
                }
        }
        __syncthreads();
    }

    // ---- epilogue: dump gates (+bias) to smem, then LSTM cell update ----
    float* Cs = (float*)smh;   // 64x128 fp32 = 32KB, overlays staging buffers
    #pragma unroll
    for (int mt = 0; mt < 2; mt++){
        int rl = wm + mt*16 + (lane >> 2);
        #pragma unroll
        for (int nj = 0; nj < 4; nj++){
            int cl = wn + nj*8 + (lane & 3)*2;
            float b0v = bias[n0 + cl], b1v = bias[n0 + cl + 1];
            Cs[rl*128 + cl]        = acc[mt][nj][0] + b0v;
            Cs[rl*128 + cl + 1]    = acc[mt][nj][1] + b1v;
            Cs[(rl+8)*128 + cl]    = acc[mt][nj][2] + b0v;
            Cs[(rl+8)*128 + cl + 1]= acc[mt][nj][3] + b1v;
        }
    }
    __syncthreads();

    const int u0 = n0 >> 2;   // global hidden-unit base (32 units per CTA)
    #pragma unroll
    for (int i = 0; i < 8; i++){
        int cidx = tid + i*256;
        int bl = cidx >> 5, jl = cidx & 31;
        float4 gv = *(const float4*)&Cs[bl*128 + jl*4];   // i, f, g, o
        float ig = sigmoidf_(gv.x);
        float fg = sigmoidf_(gv.y);
        float gg = tanhf(gv.z);
        float og = sigmoidf_(gv.w);
        int gb = m0 + bl;
        int ju = u0 + jl;
        float c = fg * g_c[gb*H_ + ju] + ig*gg;
        g_c[gb*H_ + ju] = c;
        float h = og * tanhf(c);
        g_h[gb*H_ + ju] = h;
        float hd = h * g_gammah[(size_t)((t+1)*B_ + gb)*H_ + ju];
        g_A16[gb*KG_ + 256 + ju] = __float2half(hd);
    }
}

// ---------------- per-step kernel: x_h, z_h, outputs, A[c_c|m] ----------------
__global__ void __launch_bounds__(256)
k_step2(int t, const float* __restrict__ x, const int* __restrict__ mask,
        const float* __restrict__ Wh, const float* __restrict__ bh,
        const float* __restrict__ Wf, const float* __restrict__ bf,
        float* __restrict__ out)
{
    __shared__ float hs[4][512];
    __shared__ float Wt[32][129];
    __shared__ float xh_s[4][128];
    __shared__ float xc_s[4][128];
    __shared__ float wfdiag[128];
    const int tid = threadIdx.x;
    const int b0  = blockIdx.x << 2;

    if (tid < 128) wfdiag[tid] = Wf[tid*F_ + tid];

    // stage h (written by previous gemm_g epilogue; zeros at t=0)
    for (int idx = tid; idx < 4*512; idx += 256)
        hs[idx >> 9][idx & 511] = g_h[(b0 + (idx >> 9))*H_ + (idx & 511)];
    __syncthreads();

    const int n  = tid & 127;
    const int hb = tid >> 7;

    // ---- x_h = h @ Wh^T + bh ----
    float acc[2] = {0.f, 0.f};
    for (int k0 = 0; k0 < H_; k0 += 32){
        for (int idx = tid; idx < 128*32; idx += 256){
            int nn = idx >> 5, kk = idx & 31;
            Wt[kk][nn] = Wh[nn*H_ + k0 + kk];
        }
        __syncthreads();
        #pragma unroll
        for (int k4 = 0; k4 < 8; k4++){
            float4 hv0 = *(const float4*)&hs[hb*2+0][k0 + k4*4];
            float4 hv1 = *(const float4*)&hs[hb*2+1][k0 + k4*4];
            #pragma unroll
            for (int c2 = 0; c2 < 4; c2++){
                float w = Wt[k4*4 + c2][n];
                acc[0] += w * ((&hv0.x)[c2]);
                acc[1] += w * ((&hv1.x)[c2]);
            }
        }
        __syncthreads();
    }

    float m_r[2], x_r[2];
    {
        float bhv = bh[n];
        #pragma unroll
        for (int i = 0; i < 2; i++){
            int b = hb*2 + i, gb = b0 + b;
            float xh = acc[i] + bhv;
            xh_s[b][n] = xh;
            int gi = gb*T_*F_ + t*F_ + n;
            float mv = (float)mask[gi];
            float xv = x[gi];
            m_r[i] = mv; x_r[i] = xv;
            xc_s[b][n] = mv*xv + (1.f - mv)*xh;
            out[3*BTF_ + gi] = xh;
        }
    }
    __syncthreads();

    // ---- z_h = x_c @ Wf^T (off-diag) + bf ----
    float acc2[2] = {0.f, 0.f};
    for (int k0 = 0; k0 < F_; k0 += 32){
        for (int idx = tid; idx < 128*32; idx += 256){
            int nn = idx >> 5, kk = idx & 31;
            Wt[kk][nn] = Wf[nn*F_ + k0 + kk];
        }
        __syncthreads();
        #pragma unroll
        for (int k4 = 0; k4 < 8; k4++){
            float4 v0 = *(const float4*)&xc_s[hb*2+0][k0 + k4*4];
            float4 v1 = *(const float4*)&xc_s[hb*2+1][k0 + k4*4];
            #pragma unroll
            for (int c2 = 0; c2 < 4; c2++){
                float w = Wt[k4*4 + c2][n];
                acc2[0] += w * ((&v0.x)[c2]);
                acc2[1] += w * ((&v1.x)[c2]);
            }
        }
        __syncthreads();
    }

    {
        float bfv = bf[n];
        #pragma unroll
        for (int i = 0; i < 2; i++){
            int b = hb*2 + i, gb = b0 + b;
            float z  = acc2[i] + bfv - xc_s[b][n]*wfdiag[n];
            float al = g_alpha[(size_t)(t*B_ + gb)*F_ + n];
            float xh = xh_s[b][n];
            float ch = al*z + (1.f - al)*xh;
            float cc = m_r[i]*x_r[i] + (1.f - m_r[i])*ch;
            int gi = gb*T_*F_ + t*F_ + n;
            out[gi]          = cc;
            out[BTF_  + gi]  = ch;
            out[2*BTF_+ gi]  = z;
            g_A16[gb*KG_ + n]       = __float2half(cc);
            g_A16[gb*KG_ + 128 + n] = __float2half(m_r[i]);
        }
    }
}

// ---------------- launch ----------------
extern "C" void kernel_launch(void* const* d_in, const int* in_sizes, int n_in,
                              void* d_out, int out_size)
{
    const float* x    = (const float*)d_in[0];
    const int*   mask = (const int*  )d_in[1];
    const float* Wdh  = (const float*)d_in[2];
    const float* bdh  = (const float*)d_in[3];
    const float* Wdx  = (const float*)d_in[4];
    const float* bdx  = (const float*)d_in[5];
    const float* Wh   = (const float*)d_in[6];
    const float* bh   = (const float*)d_in[7];
    const float* Wf   = (const float*)d_in[8];
    const float* bf   = (const float*)d_in[9];
    const float* Wc   = (const float*)d_in[10];
    const float* bc   = (const float*)d_in[11];
    const float* Wih  = (const float*)d_in[12];
    const float* Whh  = (const float*)d_in[13];
    const float* bih  = (const float*)d_in[14];
    const float* bhh  = (const float*)d_in[15];
    float* out = (float*)d_out;

    void *pD16, *pA216, *pA16, *pWg16, *pBgR;
    void *pWdh16, *pWdhR, *pWc16, *pWcR;
    void *pGammah, *pAlpha;
    cudaGetSymbolAddress(&pD16,    g_d16);
    cudaGetSymbolAddress(&pA216,   g_A216);
    cudaGetSymbolAddress(&pA16,    g_A16);
    cudaGetSymbolAddress(&pWg16,   g_Wg16);
    cudaGetSymbolAddress(&pBgR,    g_bgR);
    cudaGetSymbolAddress(&pWdh16,  g_Wdh16);
    cudaGetSymbolAddress(&pWdhR,   g_WdhR);
    cudaGetSymbolAddress(&pWc16,   g_Wc16);
    cudaGetSymbolAddress(&pWcR,    g_WcR);
    cudaGetSymbolAddress(&pGammah, g_gammah);
    cudaGetSymbolAddress(&pAlpha,  g_alpha);

    cudaFuncSetAttribute(gemm_2p<1>, cudaFuncAttributeMaxDynamicSharedMemorySize, SM2P);
    cudaFuncSetAttribute(gemm_2p<2>, cudaFuncAttributeMaxDynamicSharedMemorySize, SM2P);
    cudaFuncSetAttribute(gemm_g,     cudaFuncAttributeMaxDynamicSharedMemorySize, SMG);

    // setup + time-parallel precomputes
    k_setup<<<2048, 256>>>(Wih, Whh, bih, bhh, Wdh, Wc);
    k_delta2<<<256, 256>>>(mask, Wdx, bdx);
    // gamma_h = exp(-relu(delta @ Wdh^T + bdh)) : [49152,128]@[128,512]
    gemm_2p<1><<<dim3(H_/128, TB_/64), 256, SM2P>>>(
        (const __half*)pD16, (const __half*)pWdh16, (const __half*)pWdhR,
        bdh, (float*)pGammah, H_, F_);
    // alpha = sigmoid([gx,m] @ Wc^T + bc) : [49152,256]@[256,128]
    gemm_2p<2><<<dim3(F_/128, TB_/64), 256, SM2P>>>(
        (const __half*)pA216, (const __half*)pWc16, (const __half*)pWcR,
        bc, (float*)pAlpha, F_, 2*F_);

    // sequential recurrence: 96 steps
    for (int t = 0; t < T_; t++){
        k_step2<<<128, 256>>>(t, x, mask, Wh, bh, Wf, bf, out);
        if (t < T_ - 1){
            // gates + fused LSTM update (produces h(t+1), c(t+1), A16 hγ slice)
            gemm_g<<<dim3(NG_/128, B_/64), 256, SMG>>>(
                (const __half*)pA16, (const __half*)pWg16, (const float*)pBgR, t);
        }
    }
}